// round 7
// baseline (speedup 1.0000x reference)
#include <cuda_runtime.h>
#include <cstdint>

// YOLO loss via algebraic stream decomposition.
//   noobj = 0.5*Sum_all(p0^2+p5^2) - 0.5*Sum_obj(p0^2+p5^2)
//   obj terms (5% of cells) gathered on the fly during the tgt scan.
// Two dense float4 grid streams (pred 47MB, tgt 39MB) at memcpy-class BW;
// obj-cell gathers hit L2 (both arrays fit in 126MB L2).
// Fused deterministic reduction (ticket + last block).

#define YS2      49
#define NT       256
#define NB       980
#define P_IT     12          // 980*256*12 = 3,010,560 = pred float4 count
#define T_IT     10          // 980*256*10 = 2,508,800 = tgt  float4 count
#define NBATCH   8192.0

__device__ double       g_partials[NB];
__device__ unsigned int g_ticket;     // zero-init; reset by last block

// Heavy path for one obj cell. Returns full obj contribution minus the
// 0.5*(p0^2+p5^2) correction (that sum is counted in the pred stream).
__device__ __noinline__ float obj_cell_loss(
    const float* __restrict__ pred, const float* __restrict__ tgt, int cell)
{
    const float* pc = pred + (size_t)cell * 30;
    const float* tc = tgt  + (size_t)cell * 25;

    const int g    = cell % YS2;
    const float gy = (float)(g / 7);
    const float gx = (float)(g % 7);

    const float p0 = __ldg(pc), p5 = __ldg(pc + 5);

    const float tx = __ldg(tc + 1), ty = __ldg(tc + 2);
    const float tw = __ldg(tc + 3), th = __ldg(tc + 4);
    const float tcx = (gx + tx) / 7.0f;
    const float tcy = (gy + ty) / 7.0f;
    const float tx1 = tcx - tw * 0.5f, ty1 = tcy - th * 0.5f;
    const float tx2 = tcx + tw * 0.5f, ty2 = tcy + th * 0.5f;
    const float area_t = (tx2 - tx1) * (ty2 - ty1);

    float bx[2][4];
    #pragma unroll
    for (int bb = 0; bb < 2; bb++)
        #pragma unroll
        for (int j = 0; j < 4; j++)
            bx[bb][j] = __ldg(pc + bb * 5 + 1 + j);

    float iou[2];
    #pragma unroll
    for (int bb = 0; bb < 2; bb++) {
        const float px = fabsf(bx[bb][0]);
        const float py = fabsf(bx[bb][1]);
        const float pw = fabsf(bx[bb][2]);
        const float ph = fabsf(bx[bb][3]);
        const float cx = (gx + px) / 7.0f;
        const float cy = (gy + py) / 7.0f;
        const float x1 = cx - pw * 0.5f, y1 = cy - ph * 0.5f;
        const float x2 = cx + pw * 0.5f, y2 = cy + ph * 0.5f;
        const float ltx = fmaxf(x1, tx1), lty = fmaxf(y1, ty1);
        const float rbx = fminf(x2, tx2), rby = fminf(y2, ty2);
        const float iw  = fmaxf(rbx - ltx, 0.0f);
        const float ih  = fmaxf(rby - lty, 0.0f);
        const float inter  = iw * ih;
        const float area_p = (x2 - x1) * (y2 - y1);
        iou[bb] = inter / (area_p + area_t - inter);
    }

    const int   best    = (iou[1] > iou[0]) ? 1 : 0;   // tie -> box 0
    const float max_iou = best ? iou[1] : iou[0];
    const float rconf   = best ? p5 : p0;

    const float dx = bx[best][0] - tx;
    const float dy = bx[best][1] - ty;
    const float xy_loss = dx * dx + dy * dy;

    const float swd = sqrtf(fabsf(bx[best][2])) - sqrtf(fabsf(tw));
    const float shd = sqrtf(fabsf(bx[best][3])) - sqrtf(fabsf(th));
    const float wh_loss = swd * swd + shd * shd;

    const float doc = rconf - max_iou;

    float cls = 0.0f;
    #pragma unroll
    for (int j = 0; j < 20; j++) {
        const float d = __ldg(pc + 10 + j) - __ldg(tc + 5 + j);
        cls += d * d;
    }

    return 5.0f * (xy_loss + wh_loss) + doc * doc + cls
         - 0.5f * (p0 * p0 + p5 * p5);
}

__global__ __launch_bounds__(NT) void yolo_loss_kernel(
    const float* __restrict__ pred, const float* __restrict__ tgt,
    float* __restrict__ out)
{
    const int tid = threadIdx.x;
    const int b   = blockIdx.x;

    float acc = 0.0f;   // obj terms
    float sq  = 0.0f;   // Sum(p0^2 + p5^2), all cells

    // ================= pred stream: masked sum of squares ================
    {
        const float4* p4 = (const float4*)pred;
        const unsigned base = (unsigned)b * (P_IT * NT) + tid;
        #pragma unroll
        for (int k0 = 0; k0 < P_IT; k0 += 4) {
            float4 v[4];
            unsigned q[4];
            #pragma unroll
            for (int i = 0; i < 4; i++) {
                q[i] = base + (k0 + i) * NT;
                v[i] = p4[q[i]];
            }
            #pragma unroll
            for (int i = 0; i < 4; i++) {
                const unsigned r = (4u * q[i]) % 30u;   // col of component 0
                const float vv[4] = {v[i].x, v[i].y, v[i].z, v[i].w};
                #pragma unroll
                for (int j = 0; j < 4; j++) {
                    unsigned c = r + j; if (c >= 30u) c -= 30u;
                    if (c == 0u || c == 5u) sq += vv[j] * vv[j];
                }
            }
        }
    }

    // ================= tgt stream: scan col0 for obj cells ===============
    {
        const float4* t4 = (const float4*)tgt;
        const unsigned base = (unsigned)b * (T_IT * NT) + tid;
        #pragma unroll
        for (int k0 = 0; k0 < T_IT; k0 += 5) {
            float4 v[5];
            unsigned q[5];
            #pragma unroll
            for (int i = 0; i < 5; i++) {
                q[i] = base + (k0 + i) * NT;
                v[i] = t4[q[i]];
            }
            #pragma unroll
            for (int i = 0; i < 5; i++) {
                const unsigned e0 = 4u * q[i];
                const unsigned r  = e0 % 25u;           // col of component 0
                const float vv[4] = {v[i].x, v[i].y, v[i].z, v[i].w};
                #pragma unroll
                for (int j = 0; j < 4; j++) {
                    unsigned c = r + j; if (c >= 25u) c -= 25u;
                    if (c == 0u && vv[j] == 1.0f)
                        acc += obj_cell_loss(pred, tgt, (int)((e0 + j) / 25u));
                }
            }
        }
    }

    acc += 0.5f * sq;

    // ---- deterministic block reduction ----
    #pragma unroll
    for (int o = 16; o > 0; o >>= 1)
        acc += __shfl_down_sync(0xffffffffu, acc, o);

    __shared__ float wsum[NT / 32];
    __shared__ int   s_last;
    const int lane = tid & 31;
    const int wrp  = tid >> 5;
    if (lane == 0) wsum[wrp] = acc;
    __syncthreads();

    if (tid == 0) {
        double s = 0.0;
        #pragma unroll
        for (int w = 0; w < NT / 32; w++) s += (double)wsum[w];
        g_partials[b] = s;
        __threadfence();
        unsigned int ticket = atomicAdd(&g_ticket, 1u);
        s_last = (ticket == NB - 1u) ? 1 : 0;
    }
    __syncthreads();

    // ---- last block: final reduction ----
    if (s_last) {
        __threadfence();
        __shared__ double dsum[NT / 32];

        double s = 0.0;
        for (int i = tid; i < NB; i += NT)
            s += g_partials[i];

        #pragma unroll
        for (int o = 16; o > 0; o >>= 1)
            s += __shfl_down_sync(0xffffffffu, s, o);

        if (lane == 0) dsum[wrp] = s;
        __syncthreads();

        if (tid == 0) {
            double total = 0.0;
            #pragma unroll
            for (int w = 0; w < NT / 32; w++) total += dsum[w];
            out[0] = (float)(total / NBATCH);
            g_ticket = 0;   // reset for next graph replay
        }
    }
}

extern "C" void kernel_launch(void* const* d_in, const int* in_sizes, int n_in,
                              void* d_out, int out_size)
{
    const float* pred = (const float*)d_in[0];
    const float* tgt  = (const float*)d_in[1];
    float* out        = (float*)d_out;

    yolo_loss_kernel<<<NB, NT>>>(pred, tgt, out);
}

// round 8
// speedup vs baseline: 1.9108x; 1.9108x over previous
#include <cuda_runtime.h>

// YOLO loss, sparsity-aware direct-load, v2 (reshaped from R5 best).
// pred [8192, 49*30] f32 (cell stride 120B, 8B-aligned -> float2 loads),
// tgt  [8192, 49*25] f32 (cell stride 100B, 4B-aligned -> scalar loads).
// t0 in {0,1}, P(obj)=0.05: 95% of cells need only t0, p0, p5.
// 1568 blocks x 128 threads, 2 cells/thread, regs capped for 11 blocks/SM.
// Fused deterministic reduction (ticket + last block).

#define YS2      49
#define NT       128
#define CPT      2
#define NB       1568            // 401408 / (128*2)
#define NBATCH   8192.0

__device__ double       g_partials[NB];
__device__ unsigned int g_ticket;     // zero-init; reset by last block

__global__ __launch_bounds__(NT, 11) void yolo_loss_kernel(
    const float* __restrict__ pred, const float* __restrict__ tgt,
    float* __restrict__ out)
{
    const int tid  = threadIdx.x;
    const int base = blockIdx.x * (NT * CPT) + tid;

    // ---- light loads: 6 independent loads issued before any branch ----
    // f01 = {pc[0], pc[1]}, f45 = {pc[4], pc[5]}  (8B-aligned: 120*i, +16)
    int    cell[CPT];
    float  t0[CPT];
    float2 f01[CPT], f45[CPT];
    #pragma unroll
    for (int k = 0; k < CPT; k++) {
        cell[k] = base + k * NT;
        const float* pc = pred + (size_t)cell[k] * 30;
        t0[k]  = __ldg(tgt + (size_t)cell[k] * 25);
        f01[k] = __ldg((const float2*)pc);
        f45[k] = __ldg((const float2*)(pc + 4));
    }

    float acc = 0.0f;

    #pragma unroll
    for (int k = 0; k < CPT; k++) {
        const float p0 = f01[k].x;
        const float p5 = f45[k].y;

        if (t0[k] == 0.0f) {
            acc += 0.5f * (p0 * p0 + p5 * p5);
        } else if (t0[k] == 1.0f) {
            const float* pc = pred + (size_t)cell[k] * 30;
            const float* tc = tgt  + (size_t)cell[k] * 25;

            const int g    = cell[k] % YS2;
            const float gy = (float)(g / 7);
            const float gx = (float)(g % 7);

            const float tx = __ldg(tc + 1), ty = __ldg(tc + 2);
            const float tw = __ldg(tc + 3), th = __ldg(tc + 4);
            const float tcx = (gx + tx) / 7.0f;
            const float tcy = (gy + ty) / 7.0f;
            const float tx1 = tcx - tw * 0.5f, ty1 = tcy - th * 0.5f;
            const float tx2 = tcx + tw * 0.5f, ty2 = tcy + th * 0.5f;
            const float area_t = (tx2 - tx1) * (ty2 - ty1);

            // pred box floats via float2 (all 8B-aligned):
            // box0: x=f01.y, y=f23.x, w=f23.y, h=f45.x
            // box1: x=f67.x, y=f67.y, w=f89.x, h=f89.y
            const float2 f23 = __ldg((const float2*)(pc + 2));
            const float2 f67 = __ldg((const float2*)(pc + 6));
            const float2 f89 = __ldg((const float2*)(pc + 8));

            float bx[2][4] = {
                { f01[k].y, f23.x, f23.y, f45[k].x },
                { f67.x,    f67.y, f89.x, f89.y    }
            };

            float iou[2];
            #pragma unroll
            for (int bb = 0; bb < 2; bb++) {
                const float px = fabsf(bx[bb][0]);
                const float py = fabsf(bx[bb][1]);
                const float pw = fabsf(bx[bb][2]);
                const float ph = fabsf(bx[bb][3]);
                const float cx = (gx + px) / 7.0f;
                const float cy = (gy + py) / 7.0f;
                const float x1 = cx - pw * 0.5f, y1 = cy - ph * 0.5f;
                const float x2 = cx + pw * 0.5f, y2 = cy + ph * 0.5f;
                const float ltx = fmaxf(x1, tx1), lty = fmaxf(y1, ty1);
                const float rbx = fminf(x2, tx2), rby = fminf(y2, ty2);
                const float iw  = fmaxf(rbx - ltx, 0.0f);
                const float ih  = fmaxf(rby - lty, 0.0f);
                const float inter  = iw * ih;
                const float area_p = (x2 - x1) * (y2 - y1);
                iou[bb] = inter / (area_p + area_t - inter);
            }

            const int   best    = (iou[1] > iou[0]) ? 1 : 0;  // tie -> box 0
            const float max_iou = best ? iou[1] : iou[0];
            const float rconf   = best ? p5 : p0;

            const float dx = bx[best][0] - tx;
            const float dy = bx[best][1] - ty;
            const float xy_loss = dx * dx + dy * dy;

            const float swd = sqrtf(fabsf(bx[best][2])) - sqrtf(fabsf(tw));
            const float shd = sqrtf(fabsf(bx[best][3])) - sqrtf(fabsf(th));
            const float wh_loss = swd * swd + shd * shd;

            const float doc = rconf - max_iou;
            const float obj_conf = doc * doc;

            // cls: pred via 10 float2 loads, tgt scalar
            float cls = 0.0f;
            #pragma unroll
            for (int j = 0; j < 10; j++) {
                const float2 pv = __ldg((const float2*)(pc + 10 + 2 * j));
                const float d0 = pv.x - __ldg(tc + 5 + 2 * j);
                const float d1 = pv.y - __ldg(tc + 6 + 2 * j);
                cls += d0 * d0 + d1 * d1;
            }

            acc += 5.0f * (xy_loss + wh_loss) + obj_conf + cls;
        }
    }

    // ---- deterministic block reduction ----
    #pragma unroll
    for (int o = 16; o > 0; o >>= 1)
        acc += __shfl_down_sync(0xffffffffu, acc, o);

    __shared__ float wsum[NT / 32];
    __shared__ int   s_last;
    const int lane = tid & 31;
    const int wrp  = tid >> 5;
    if (lane == 0) wsum[wrp] = acc;
    __syncthreads();

    if (tid == 0) {
        double s = 0.0;
        #pragma unroll
        for (int w = 0; w < NT / 32; w++) s += (double)wsum[w];
        g_partials[blockIdx.x] = s;
        __threadfence();
        unsigned int ticket = atomicAdd(&g_ticket, 1u);
        s_last = (ticket == NB - 1u) ? 1 : 0;
    }
    __syncthreads();

    // ---- last block: final reduction over all partials ----
    if (s_last) {
        __threadfence();
        __shared__ double dsum[NT / 32];

        double s = 0.0;
        for (int i = tid; i < NB; i += NT)
            s += g_partials[i];

        #pragma unroll
        for (int o = 16; o > 0; o >>= 1)
            s += __shfl_down_sync(0xffffffffu, s, o);

        if (lane == 0) dsum[wrp] = s;
        __syncthreads();

        if (tid == 0) {
            double total = 0.0;
            #pragma unroll
            for (int w = 0; w < NT / 32; w++) total += dsum[w];
            out[0] = (float)(total / NBATCH);
            g_ticket = 0;   // reset for next graph replay
        }
    }
}

extern "C" void kernel_launch(void* const* d_in, const int* in_sizes, int n_in,
                              void* d_out, int out_size)
{
    const float* pred = (const float*)d_in[0];
    const float* tgt  = (const float*)d_in[1];
    float* out        = (float*)d_out;

    yolo_loss_kernel<<<NB, NT>>>(pred, tgt, out);
}